// round 15
// baseline (speedup 1.0000x reference)
#include <cuda_runtime.h>
#include <math.h>

#define SQ 2048
#define NB 8
#define HDIM 768
#define HD 384
#define NG 1536
#define NT 64
#define NU 32

// ---------------- device scratch (static, no runtime alloc) ----------------
__device__ float    g_xproj[2u * SQ * NB * NG];   // [dir][t][b][gate_row]
__device__ float    g_hbuf [8 * 2 * 2 * HD];      // fallback path exchange
__device__ unsigned g_flag [128 * 32];            // fallback path flags
__device__ float    g_mp   [NB * NU * HDIM];      // [b][u][h] pooled features
__device__ float    g_emb  [NB * NU * HDIM];      // [b][u][h] routed embeddings

// ---------------- helpers ---------------------------------------------------
__device__ __forceinline__ unsigned long long fma2(
    unsigned long long a, unsigned long long b, unsigned long long c) {
    unsigned long long d;
    asm("fma.rn.f32x2 %0, %1, %2, %3;" : "=l"(d) : "l"(a), "l"(b), "l"(c));
    return d;
}
__device__ __forceinline__ float2 upk2(unsigned long long v) {
    float2 f;
    asm("mov.b64 {%0,%1}, %2;" : "=f"(f.x), "=f"(f.y) : "l"(v));
    return f;
}
__device__ __forceinline__ unsigned smem_u32(const void* p) {
    unsigned a;
    asm("{ .reg .u64 t; cvta.to.shared.u64 t, %1; cvt.u32.u64 %0, t; }"
        : "=r"(a) : "l"(p));
    return a;
}
__device__ __forceinline__ void mbar_wait(unsigned addr, unsigned phase) {
    unsigned done;
    do {
        asm volatile(
            "{\n\t.reg .pred p;\n\t"
            "mbarrier.try_wait.parity.acquire.cta.shared::cta.b64 p, [%1], %2, 0x989680;\n\t"
            "selp.b32 %0, 1, 0, p;\n\t}"
            : "=r"(done) : "r"(addr), "r"(phase) : "memory");
    } while (!done);
}

// ---------------- pad kernel (ncu steering: launch #4 = k_gemm) ------------
__global__ void k_pad() {}

// ---------------- flag reset (fallback path only) --------------------------
__global__ void k_reset()
{
    int i = blockIdx.x * 256 + threadIdx.x;
    if (i < 128 * 32) g_flag[i] = 0u;
}

// ---------------- K1: input projection GEMM, 64x128 tiles ------------------
// vs R8: CTA tile 64(m) x 128(n), thread tile 4x8 (32 acc regs) -> 3 CTAs/SM
// (24 warps) instead of 2 (16 warps). Same loop/sync/STS structure as R8.
__global__ void __launch_bounds__(256, 3) k_gemm(
    const float* __restrict__ X,
    const float* __restrict__ Wf, const float* __restrict__ Wb,
    const float* __restrict__ bihf, const float* __restrict__ bhhf,
    const float* __restrict__ bihb, const float* __restrict__ bhhb)
{
    const int dir = blockIdx.z;
    const float* W = dir ? Wb : Wf;
    const int n0 = blockIdx.x * 128;
    const int m0 = blockIdx.y * 64;

    __shared__ float As[8][64];
    __shared__ float Bs[8][128];

    const int tid = threadIdx.x;
    const int brow = tid >> 1, bhalf = tid & 1;   // B loader: all 256 threads
    const int arow = (tid & 127) >> 1, ahalf = tid & 1;  // A loader: tid<128
    const int tx = tid & 15, ty = tid >> 4;       // compute: 16(n) x 16(m)

    float acc[4][8];
#pragma unroll
    for (int i = 0; i < 4; i++)
#pragma unroll
        for (int j = 0; j < 8; j++) acc[i][j] = 0.f;

    const float* xptr = X + (m0 + arow) * 768 + ahalf * 4;
    const float* wptr = W + (n0 + brow) * 768 + bhalf * 4;

    for (int kt = 0; kt < 768; kt += 8) {
        float4 bv = *(const float4*)(wptr + kt);
        float4 av;
        if (tid < 128) av = *(const float4*)(xptr + kt);
        __syncthreads();
        Bs[bhalf * 4 + 0][brow] = bv.x; Bs[bhalf * 4 + 1][brow] = bv.y;
        Bs[bhalf * 4 + 2][brow] = bv.z; Bs[bhalf * 4 + 3][brow] = bv.w;
        if (tid < 128) {
            As[ahalf * 4 + 0][arow] = av.x; As[ahalf * 4 + 1][arow] = av.y;
            As[ahalf * 4 + 2][arow] = av.z; As[ahalf * 4 + 3][arow] = av.w;
        }
        __syncthreads();
#pragma unroll
        for (int k = 0; k < 8; k++) {
            float a[4], b[8];
            *(float4*)(a)     = *(const float4*)&As[k][ty * 4];
            *(float4*)(b)     = *(const float4*)&Bs[k][tx * 8];
            *(float4*)(b + 4) = *(const float4*)&Bs[k][tx * 8 + 4];
#pragma unroll
            for (int i = 0; i < 4; i++)
#pragma unroll
                for (int j = 0; j < 8; j++)
                    acc[i][j] = fmaf(a[i], b[j], acc[i][j]);
        }
    }

    const float* bi = dir ? bihb : bihf;
    const float* bh = dir ? bhhb : bhhf;
    float bias[8];
#pragma unroll
    for (int j = 0; j < 8; j++) {
        int n = n0 + tx * 8 + j;
        bias[j] = bi[n] + bh[n];
    }
#pragma unroll
    for (int i = 0; i < 4; i++) {
        int m = m0 + ty * 4 + i;
        int s = m & 2047, bb = m >> 11;
        int t = dir ? (2047 - s) : s;
        float* o = g_xproj + ((((dir * SQ + t) * NB + bb) * NG) + n0 + tx * 8);
        float4 v0, v1;
        v0.x = acc[i][0] + bias[0]; v0.y = acc[i][1] + bias[1];
        v0.z = acc[i][2] + bias[2]; v0.w = acc[i][3] + bias[3];
        v1.x = acc[i][4] + bias[4]; v1.y = acc[i][5] + bias[5];
        v1.z = acc[i][6] + bias[6]; v1.w = acc[i][7] + bias[7];
        *(float4*)(o)     = v0;
        *(float4*)(o + 4) = v1;
    }
}

// ---------------- K2a: cluster BiLSTM (R11 version — best measured) --------
__global__ void __launch_bounds__(256, 1) __cluster_dims__(16, 1, 1)
k_lstm_cl(const float* __restrict__ Whhf, const float* __restrict__ Whhb,
          const int* __restrict__ utter)
{
    unsigned c;
    asm("mov.u32 %0, %%cluster_ctarank;" : "=r"(c));
    const int grp = blockIdx.x >> 4;
    const int dir = grp >> 2;
    const int bp  = grp & 3;
    const int j0  = (int)c * 24;
    const float* Whh = dir ? Whhb : Whhf;
    const int tid = threadIdx.x;
    const int wid = tid >> 5, lane = tid & 31;
    const int g2   = wid >> 1;
    const int half = wid & 1;
    const int jw   = j0 + half * 12;

    __shared__ __align__(16) float h_s[2][2][HD];   // [buf][b2][j]
    __shared__ float gate_s[4][24][2];
    __shared__ float segmax_s[2][33][24];
    __shared__ __align__(8) unsigned long long mbar[2];

    for (int i = tid; i < 2 * 2 * HD; i += 256) (&h_s[0][0][0])[i] = 0.f;
    for (int i = tid; i < 2 * 33 * 24; i += 256) (&segmax_s[0][0][0])[i] = 0.f;

    const unsigned mb0 = smem_u32(&mbar[0]);
    const unsigned mb1 = smem_u32(&mbar[1]);
    if (tid == 0) {
        asm volatile("mbarrier.init.shared.b64 [%0], %1;" :: "r"(mb0), "r"(1u) : "memory");
        asm volatile("mbarrier.init.shared.b64 [%0], %1;" :: "r"(mb1), "r"(1u) : "memory");
    }
    __syncthreads();
    if (tid == 0) {   // arm both buffers for h(0), h(1)
        asm volatile("mbarrier.arrive.expect_tx.shared.b64 _, [%0], %1;" :: "r"(mb0), "r"(3072u) : "memory");
        asm volatile("mbarrier.arrive.expect_tx.shared.b64 _, [%0], %1;" :: "r"(mb1), "r"(3072u) : "memory");
    }

    unsigned long long wp[12][6];
#pragma unroll
    for (int i = 0; i < 12; i++) {
        const float* wr = Whh + (long)(g2 * HD + jw + i) * HD + lane * 2;
#pragma unroll
        for (int q = 0; q < 6; q++)
            wp[i][q] = *(const unsigned long long*)(wr + 64 * q);
    }

    const int jj_a = tid >> 1, b2_a = tid & 1;
    const int batch_a = bp * 2 + b2_a;
    float c_state = 0.f;

    __syncthreads();
    asm volatile("barrier.cluster.arrive.aligned;" ::: "memory");
    asm volatile("barrier.cluster.wait.aligned;" ::: "memory");

    for (int t = 0; t < SQ; t++) {
        float xp0 = 0.f, xp1 = 0.f, xp2 = 0.f, xp3 = 0.f;
        int useg = 0;
        if (tid < 48) {
            int pos = dir ? (SQ - 1 - t) : t;
            const float* xb = g_xproj +
                ((((long)dir * SQ + t) * NB + batch_a) * NG) + j0 + jj_a;
            xp0 = xb[0]; xp1 = xb[HD]; xp2 = xb[2 * HD]; xp3 = xb[3 * HD];
            int u = utter[batch_a * SQ + pos];
            useg = u > 0 ? u : 0;
        }

        if (t > 0) {
            unsigned mb = ((t - 1) & 1) ? mb1 : mb0;
            mbar_wait(mb, ((unsigned)(t - 1) >> 1) & 1u);
            if (tid == 0)
                asm volatile("mbarrier.arrive.expect_tx.shared.b64 _, [%0], %1;"
                             :: "r"(mb), "r"(3072u) : "memory");
        }

        const int br = (t + 1) & 1;
#pragma unroll
        for (int b2 = 0; b2 < 2; b2++) {
            unsigned long long p2[12];
#pragma unroll
            for (int i = 0; i < 12; i++) p2[i] = 0ull;
#pragma unroll
            for (int q = 0; q < 6; q++) {
                unsigned long long hq =
                    *(const unsigned long long*)&h_s[br][b2][lane * 2 + 64 * q];
#pragma unroll
                for (int i = 0; i < 12; i++)
                    p2[i] = fma2(wp[i][q], hq, p2[i]);
            }
#pragma unroll
            for (int i = 0; i < 12; i++) {
                float2 f = upk2(p2[i]);
                float v = f.x + f.y;
                v += __shfl_xor_sync(0xffffffffu, v, 16);
                v += __shfl_xor_sync(0xffffffffu, v, 8);
                v += __shfl_xor_sync(0xffffffffu, v, 4);
                v += __shfl_xor_sync(0xffffffffu, v, 2);
                v += __shfl_xor_sync(0xffffffffu, v, 1);
                if (lane == 0) gate_s[g2][half * 12 + i][b2] = v;
            }
        }
        __syncthreads();

        // activation + DSMEM broadcast + fused segment max
        if (tid < 48) {
            float vi = gate_s[0][jj_a][b2_a] + xp0;
            float vf = gate_s[1][jj_a][b2_a] + xp1;
            float vg = gate_s[2][jj_a][b2_a] + xp2;
            float vo = gate_s[3][jj_a][b2_a] + xp3;
            float si = 1.f / (1.f + __expf(-vi));
            float sf = 1.f / (1.f + __expf(-vf));
            float so = 1.f / (1.f + __expf(-vo));
            float tg, tc;
            asm("tanh.approx.f32 %0, %1;" : "=f"(tg) : "f"(vg));
            c_state = sf * c_state + si * tg;
            asm("tanh.approx.f32 %0, %1;" : "=f"(tc) : "f"(c_state));
            float h = so * tc;

            unsigned val   = __float_as_uint(h);
            unsigned laddr = smem_u32(&h_s[t & 1][b2_a][j0 + jj_a]);
            unsigned lmbar = (t & 1) ? mb1 : mb0;
#pragma unroll
            for (int p = 0; p < 16; p++) {
                unsigned ra, rb;
                asm("mapa.shared::cluster.u32 %0, %1, %2;" : "=r"(ra) : "r"(laddr), "r"(p));
                asm("mapa.shared::cluster.u32 %0, %1, %2;" : "=r"(rb) : "r"(lmbar), "r"(p));
                asm volatile(
                    "st.async.shared::cluster.mbarrier::complete_tx::bytes.u32 [%0], %1, [%2];"
                    :: "r"(ra), "r"(val), "r"(rb) : "memory");
            }
            float* sm = &segmax_s[b2_a][useg][jj_a];
            *sm = fmaxf(*sm, h);
        }
    }

    mbar_wait(mb1, ((unsigned)(SQ - 1) >> 1) & 1u);

    if (tid < 48) {
        for (int u = 1; u <= NU; u++)
            g_mp[(batch_a * NU + (u - 1)) * HDIM + dir * HD + j0 + jj_a] =
                segmax_s[b2_a][u][jj_a];
    }
}

// ---------------- K2b: fallback BiLSTM (R8 version, L2 flag exchange) ------
__global__ void __launch_bounds__(256, 1) k_lstm(
    const float* __restrict__ Whhf, const float* __restrict__ Whhb,
    const int* __restrict__ utter)
{
    const int grp = blockIdx.x >> 4;
    const int c   = blockIdx.x & 15;
    const int dir = grp >> 2;
    const int bp  = grp & 3;
    const int j0  = c * 24;
    const float* Whh = dir ? Whhb : Whhf;
    const int tid = threadIdx.x;
    const int wid = tid >> 5, lane = tid & 31;
    const int g2   = wid >> 1;
    const int half = wid & 1;
    const int jw   = j0 + half * 12;

    __shared__ __align__(16) float h_s[2][HD];
    __shared__ float gate_s[4][24][2];
    __shared__ float segmax_s[2][33][24];

    for (int i = tid; i < 2 * HD; i += 256) (&h_s[0][0])[i] = 0.f;
    for (int i = tid; i < 2 * 33 * 24; i += 256) (&segmax_s[0][0][0])[i] = 0.f;

    unsigned long long wp[12][6];
#pragma unroll
    for (int i = 0; i < 12; i++) {
        const float* wr = Whh + (long)(g2 * HD + jw + i) * HD + lane * 2;
#pragma unroll
        for (int q = 0; q < 6; q++)
            wp[i][q] = *(const unsigned long long*)(wr + 64 * q);
    }

    const int jj_a = tid >> 1, b2_a = tid & 1;
    const int batch_a = bp * 2 + b2_a;
    float c_state = 0.f;
    unsigned* flags = g_flag + grp * 16 * 32;
    float* hbase = g_hbuf + grp * 2 * 2 * HD;

    __syncthreads();

    for (int t = 0; t < SQ; t++) {
        float xp0 = 0.f, xp1 = 0.f, xp2 = 0.f, xp3 = 0.f;
        int useg = 0;
        if (tid < 48) {
            int pos = dir ? (SQ - 1 - t) : t;
            const float* xb = g_xproj +
                ((((long)dir * SQ + t) * NB + batch_a) * NG) + j0 + jj_a;
            xp0 = xb[0]; xp1 = xb[HD]; xp2 = xb[2 * HD]; xp3 = xb[3 * HD];
            int u = utter[batch_a * SQ + pos];
            useg = u > 0 ? u : 0;
        }

#pragma unroll
        for (int b2 = 0; b2 < 2; b2++) {
            unsigned long long p2[12];
#pragma unroll
            for (int i = 0; i < 12; i++) p2[i] = 0ull;
#pragma unroll
            for (int q = 0; q < 6; q++) {
                unsigned long long hq =
                    *(const unsigned long long*)&h_s[b2][lane * 2 + 64 * q];
#pragma unroll
                for (int i = 0; i < 12; i++)
                    p2[i] = fma2(wp[i][q], hq, p2[i]);
            }
#pragma unroll
            for (int i = 0; i < 12; i++) {
                float2 f = upk2(p2[i]);
                float v = f.x + f.y;
                v += __shfl_xor_sync(0xffffffffu, v, 16);
                v += __shfl_xor_sync(0xffffffffu, v, 8);
                v += __shfl_xor_sync(0xffffffffu, v, 4);
                v += __shfl_xor_sync(0xffffffffu, v, 2);
                v += __shfl_xor_sync(0xffffffffu, v, 1);
                if (lane == 0) gate_s[g2][half * 12 + i][b2] = v;
            }
        }
        __syncthreads();

        if (tid < 48) {
            float vi = gate_s[0][jj_a][b2_a] + xp0;
            float vf = gate_s[1][jj_a][b2_a] + xp1;
            float vg = gate_s[2][jj_a][b2_a] + xp2;
            float vo = gate_s[3][jj_a][b2_a] + xp3;
            float si = 1.f / (1.f + __expf(-vi));
            float sf = 1.f / (1.f + __expf(-vf));
            float so = 1.f / (1.f + __expf(-vo));
            float tg, tc;
            asm("tanh.approx.f32 %0, %1;" : "=f"(tg) : "f"(vg));
            c_state = sf * c_state + si * tg;
            asm("tanh.approx.f32 %0, %1;" : "=f"(tc) : "f"(c_state));
            float h = so * tc;
            __stcg(hbase + (t & 1) * 2 * HD + b2_a * HD + j0 + jj_a, h);
            float* sm = &segmax_s[b2_a][useg][jj_a];
            *sm = fmaxf(*sm, h);
        }
        __syncthreads();

        if (tid == 0) {
            asm volatile("st.release.gpu.global.u32 [%0], %1;"
                         :: "l"(flags + c * 32), "r"((unsigned)(t + 1)) : "memory");
        }
        if (wid == 0) {
            unsigned tgt = (unsigned)(t + 1);
            const unsigned* fp = flags + lane * 32;
            bool ok;
            do {
                unsigned v = tgt;
                if (lane < 16)
                    asm volatile("ld.acquire.gpu.global.u32 %0, [%1];"
                                 : "=r"(v) : "l"(fp) : "memory");
                ok = __all_sync(0xffffffffu, v >= tgt);
            } while (!ok);
        }
        __syncthreads();

        if (tid < 192) {
            const float4* src = (const float4*)(hbase + (t & 1) * 2 * HD);
            ((float4*)(&h_s[0][0]))[tid] = __ldcg(src + tid);
        }
        __syncthreads();
    }

    if (tid < 48) {
        for (int u = 1; u <= NU; u++)
            g_mp[(batch_a * NU + (u - 1)) * HDIM + dir * HD + j0 + jj_a] =
                segmax_s[b2_a][u][jj_a];
    }
}

// ---------------- K3: topic softmax routing ---------------------------------
__global__ void __launch_bounds__(256) k_route(
    const float* __restrict__ tw, const float* __restrict__ tb,
    const float* __restrict__ table)
{
    const int b = blockIdx.x >> 5;
    const int u = blockIdx.x & 31;
    __shared__ float mp_s[768];
    __shared__ float lp_s[4][64];
    __shared__ float l_s[64], e_s[64];
    const int tid = threadIdx.x;
    const float* mpr = g_mp + (b * NU + u) * HDIM;
    for (int i = tid; i < 192; i += 256)
        ((float4*)mp_s)[i] = ((const float4*)mpr)[i];
    __syncthreads();
    {
        const int topic = tid & 63, slice = tid >> 6;
        float acc = 0.f;
        const float* wr = tw + topic * 768 + slice * 192;
        const float* ms = mp_s + slice * 192;
        for (int k = 0; k < 192; k += 4) {
            float4 wv = *(const float4*)(wr + k);
            acc = fmaf(wv.x, ms[k], acc);
            acc = fmaf(wv.y, ms[k + 1], acc);
            acc = fmaf(wv.z, ms[k + 2], acc);
            acc = fmaf(wv.w, ms[k + 3], acc);
        }
        lp_s[slice][topic] = acc;
    }
    __syncthreads();
    if (tid < 64)
        l_s[tid] = lp_s[0][tid] + lp_s[1][tid] + lp_s[2][tid] + lp_s[3][tid] + tb[tid];
    __syncthreads();
    if (tid < 64) {
        float mx = -1e30f;
        for (int i = 0; i < 64; i++) mx = fmaxf(mx, l_s[i]);
        e_s[tid] = expf(l_s[tid] - mx);
    }
    __syncthreads();
    float ssum = 0.f;
    for (int i = 0; i < 64; i++) ssum += e_s[i];
    float inv = 1.f / ssum;
    for (int h = tid; h < 768; h += 256) {
        float acc = 0.f;
        for (int tt = 0; tt < 64; tt++)
            acc = fmaf(e_s[tt], table[tt * 768 + h], acc);
        g_emb[(b * NU + u) * HDIM + h] = acc * inv;
    }
}

// ---------------- K4: scatter back to token positions -----------------------
__global__ void __launch_bounds__(256) k_scatter(
    const int* __restrict__ utter, float* __restrict__ out)
{
    int v = blockIdx.x * 256 + threadIdx.x;
    int m = v / 192;
    int h4 = v - m * 192;
    int u = __ldg(utter + m);
    float4 o = make_float4(0.f, 0.f, 0.f, 0.f);
    if (u != 0) {
        int idx = u > 0 ? u - 1 : -u - 1;
        if (idx > 31) idx = 31;
        int bb = m >> 11;
        float4 gv = *(const float4*)(g_emb + (bb * NU + idx) * HDIM + h4 * 4);
        float sc = u > 0 ? 1.f : 2.f;
        o.x = gv.x * sc; o.y = gv.y * sc; o.z = gv.z * sc; o.w = gv.w * sc;
    }
    ((float4*)out)[v] = o;
}

// ---------------- launch -----------------------------------------------------
extern "C" void kernel_launch(void* const* d_in, const int* in_sizes, int n_in,
                              void* d_out, int out_size)
{
    const float* X     = (const float*)d_in[0];
    const float* Wihf  = (const float*)d_in[1];
    const float* Whhf  = (const float*)d_in[2];
    const float* bihf  = (const float*)d_in[3];
    const float* bhhf  = (const float*)d_in[4];
    const float* Wihb  = (const float*)d_in[5];
    const float* Whhb  = (const float*)d_in[6];
    const float* bihb  = (const float*)d_in[7];
    const float* bhhb  = (const float*)d_in[8];
    const float* tw    = (const float*)d_in[9];
    const float* tb    = (const float*)d_in[10];
    const float* table = (const float*)d_in[11];
    const int*   utter = (const int*)d_in[12];

    // cluster probe (attr-free first; clusters independent so >=4 suffices)
    cudaFuncSetAttribute(k_lstm_cl,
                         cudaFuncAttributeNonPortableClusterSizeAllowed, 1);
    int ncl = 0;
    {
        cudaLaunchConfig_t cfg = {};
        cfg.gridDim  = dim3(128, 1, 1);
        cfg.blockDim = dim3(256, 1, 1);
        cfg.dynamicSmemBytes = 0;
        cfg.stream = 0;
        cfg.attrs = 0;
        cfg.numAttrs = 0;
        cudaError_t e1 = cudaOccupancyMaxActiveClusters(&ncl, k_lstm_cl, &cfg);
        if (e1 != cudaSuccess || ncl <= 0) {
            cudaGetLastError();
            cudaLaunchAttribute a[1];
            a[0].id = cudaLaunchAttributeClusterDimension;
            a[0].val.clusterDim.x = 16;
            a[0].val.clusterDim.y = 1;
            a[0].val.clusterDim.z = 1;
            cfg.attrs = a;
            cfg.numAttrs = 1;
            ncl = 0;
            cudaError_t e2 = cudaOccupancyMaxActiveClusters(&ncl, k_lstm_cl, &cfg);
            if (e2 != cudaSuccess) ncl = 0;
        }
        cudaGetLastError();
    }
    bool use_cl = (ncl >= 4);

    // 3 pads: ncu capture (launch #4) lands on k_gemm
    k_pad<<<1, 32>>>();
    k_pad<<<1, 32>>>();
    k_pad<<<1, 32>>>();
    k_gemm<<<dim3(12, 256, 2), 256>>>(X, Wihf, Wihb, bihf, bhhf, bihb, bhhb);
    if (use_cl) {
        k_lstm_cl<<<128, 256>>>(Whhf, Whhb, utter);
    } else {
        k_reset<<<16, 256>>>();
        k_lstm<<<128, 256>>>(Whhf, Whhb, utter);
    }
    k_route<<<256, 256>>>(tw, tb, table);
    k_scatter<<<12288, 256>>>(utter, (float*)d_out);
}

// round 17
// speedup vs baseline: 1.2806x; 1.2806x over previous
#include <cuda_runtime.h>
#include <cuda_bf16.h>
#include <math.h>

#define SQ 2048
#define NB 8
#define HDIM 768
#define HD 384
#define NG 1536
#define NT 64
#define NU 32

// ---------------- device scratch (static, no runtime alloc) ----------------
__device__ float          g_xproj[2u * SQ * NB * NG];   // [dir][t][b][gate_row]
__device__ float          g_hbuf [8 * 2 * 2 * HD];      // fallback exchange
__device__ unsigned       g_flag [128 * 32];            // fallback flags
__device__ float          g_mp   [NB * NU * HDIM];
__device__ float          g_emb  [NB * NU * HDIM];
__device__ __nv_bfloat16  g_xh[16384u * 768], g_xl[16384u * 768];
__device__ __nv_bfloat16  g_wh[2u * 1536 * 768], g_wl[2u * 1536 * 768];

// ---------------- helpers ---------------------------------------------------
__device__ __forceinline__ unsigned long long fma2(
    unsigned long long a, unsigned long long b, unsigned long long c) {
    unsigned long long d;
    asm("fma.rn.f32x2 %0, %1, %2, %3;" : "=l"(d) : "l"(a), "l"(b), "l"(c));
    return d;
}
__device__ __forceinline__ float2 upk2(unsigned long long v) {
    float2 f;
    asm("mov.b64 {%0,%1}, %2;" : "=f"(f.x), "=f"(f.y) : "l"(v));
    return f;
}
__device__ __forceinline__ unsigned smem_u32(const void* p) {
    unsigned a;
    asm("{ .reg .u64 t; cvta.to.shared.u64 t, %1; cvt.u32.u64 %0, t; }"
        : "=r"(a) : "l"(p));
    return a;
}
__device__ __forceinline__ void mbar_wait(unsigned addr, unsigned phase) {
    unsigned done;
    do {
        asm volatile(
            "{\n\t.reg .pred p;\n\t"
            "mbarrier.try_wait.parity.acquire.cta.shared::cta.b64 p, [%1], %2, 0x989680;\n\t"
            "selp.b32 %0, 1, 0, p;\n\t}"
            : "=r"(done) : "r"(addr), "r"(phase) : "memory");
    } while (!done);
}

// mma.sync m16n8k16 bf16 -> f32 (baseline PTX, no 'a' target needed)
#define MMA16816(d, a, b)                                                     \
    asm volatile(                                                             \
        "mma.sync.aligned.m16n8k16.row.col.f32.bf16.bf16.f32 "                \
        "{%0,%1,%2,%3}, {%4,%5,%6,%7}, {%8,%9}, {%0,%1,%2,%3};"               \
        : "+f"((d)[0]), "+f"((d)[1]), "+f"((d)[2]), "+f"((d)[3])              \
        : "r"((a)[0]), "r"((a)[1]), "r"((a)[2]), "r"((a)[3]),                 \
          "r"((b)[0]), "r"((b)[1]))

// ---------------- split-precision convert -----------------------------------
__global__ void k_cvt(const float* __restrict__ src,
                      __nv_bfloat16* __restrict__ hi,
                      __nv_bfloat16* __restrict__ lo, int n)
{
    int i = blockIdx.x * 256 + threadIdx.x;
    if (i < n) {
        float f = src[i];
        __nv_bfloat16 h = __float2bfloat16(f);
        hi[i] = h;
        lo[i] = __float2bfloat16(f - __bfloat162float(h));
    }
}

// ---------------- flag reset (fallback path only) --------------------------
__global__ void k_reset()
{
    int i = blockIdx.x * 256 + threadIdx.x;
    if (i < 128 * 32) g_flag[i] = 0u;
}

// ---------------- K1: tensor-core GEMM (mma.sync bf16x3) --------------------
// CTA 64(m) x 128(n), 8 warps = 2(m) x 4(n), warp tile 32x32.
// K in chunks of 32 (pitch-40 smem rows: conflict-free fragment loads).
// 3 passes per k16: Ah*Bh + Ah*Bl + Al*Bh accumulate in fp32.
__global__ void __launch_bounds__(256) k_gemm_mma(
    const __nv_bfloat16* __restrict__ xh, const __nv_bfloat16* __restrict__ xl,
    const __nv_bfloat16* __restrict__ wh, const __nv_bfloat16* __restrict__ wl,
    const float* __restrict__ bihf, const float* __restrict__ bhhf,
    const float* __restrict__ bihb, const float* __restrict__ bhhb)
{
    __shared__ __align__(16) __nv_bfloat16 Ah[64][40], Al[64][40];
    __shared__ __align__(16) __nv_bfloat16 Bh[128][40], Bl[128][40];

    const int dir = blockIdx.z;
    const int n0 = blockIdx.x * 128;
    const int m0 = blockIdx.y * 64;
    const int tid = threadIdx.x;
    const int wid = tid >> 5, lane = tid & 31;
    const int grp = lane >> 2, tg = lane & 3;
    const int wm = wid & 1, wn = wid >> 1;

    float acc[2][4][4];
#pragma unroll
    for (int mt = 0; mt < 2; mt++)
#pragma unroll
        for (int nt = 0; nt < 4; nt++)
#pragma unroll
            for (int e = 0; e < 4; e++) acc[mt][nt][e] = 0.f;

    const long xb = (long)m0 * 768;
    const long wb = (long)(dir * 1536 + n0) * 768;
    const int arow = tid >> 2, akq = tid & 3;     // A loader: 1 uint4 each

    for (int k0 = 0; k0 < 768; k0 += 32) {
        __syncthreads();
        *(uint4*)&Ah[arow][akq * 8] =
            *(const uint4*)(xh + xb + (long)arow * 768 + k0 + akq * 8);
        *(uint4*)&Al[arow][akq * 8] =
            *(const uint4*)(xl + xb + (long)arow * 768 + k0 + akq * 8);
#pragma unroll
        for (int i = 0; i < 2; i++) {
            int idx = tid + i * 256;
            int row = idx >> 2, kq = idx & 3;
            *(uint4*)&Bh[row][kq * 8] =
                *(const uint4*)(wh + wb + (long)row * 768 + k0 + kq * 8);
            *(uint4*)&Bl[row][kq * 8] =
                *(const uint4*)(wl + wb + (long)row * 768 + k0 + kq * 8);
        }
        __syncthreads();

#pragma unroll
        for (int ks = 0; ks < 2; ks++) {
            const int kk = ks * 16;
            unsigned ah[2][4], al[2][4], bhf[4][2], blf[4][2];
#pragma unroll
            for (int mt = 0; mt < 2; mt++) {
                int r0 = wm * 32 + mt * 16 + grp;
                ah[mt][0] = *(const unsigned*)&Ah[r0][kk + tg * 2];
                ah[mt][1] = *(const unsigned*)&Ah[r0 + 8][kk + tg * 2];
                ah[mt][2] = *(const unsigned*)&Ah[r0][kk + 8 + tg * 2];
                ah[mt][3] = *(const unsigned*)&Ah[r0 + 8][kk + 8 + tg * 2];
                al[mt][0] = *(const unsigned*)&Al[r0][kk + tg * 2];
                al[mt][1] = *(const unsigned*)&Al[r0 + 8][kk + tg * 2];
                al[mt][2] = *(const unsigned*)&Al[r0][kk + 8 + tg * 2];
                al[mt][3] = *(const unsigned*)&Al[r0 + 8][kk + 8 + tg * 2];
            }
#pragma unroll
            for (int nt = 0; nt < 4; nt++) {
                int c = wn * 32 + nt * 8 + grp;
                bhf[nt][0] = *(const unsigned*)&Bh[c][kk + tg * 2];
                bhf[nt][1] = *(const unsigned*)&Bh[c][kk + 8 + tg * 2];
                blf[nt][0] = *(const unsigned*)&Bl[c][kk + tg * 2];
                blf[nt][1] = *(const unsigned*)&Bl[c][kk + 8 + tg * 2];
            }
#pragma unroll
            for (int mt = 0; mt < 2; mt++)
#pragma unroll
                for (int nt = 0; nt < 4; nt++) {
                    MMA16816(acc[mt][nt], ah[mt], bhf[nt]);
                    MMA16816(acc[mt][nt], ah[mt], blf[nt]);
                    MMA16816(acc[mt][nt], al[mt], bhf[nt]);
                }
        }
    }

    // epilogue: c0,c1 -> (grp, tg*2..+1); c2,c3 -> (grp+8, tg*2..+1)
    const float* bi  = dir ? bihb : bihf;
    const float* bh2 = dir ? bhhb : bhhf;
    float bias[4][2];
#pragma unroll
    for (int nt = 0; nt < 4; nt++) {
        int n = n0 + wn * 32 + nt * 8 + tg * 2;
        bias[nt][0] = bi[n] + bh2[n];
        bias[nt][1] = bi[n + 1] + bh2[n + 1];
    }
#pragma unroll
    for (int mt = 0; mt < 2; mt++) {
#pragma unroll
        for (int hf = 0; hf < 2; hf++) {
            int m = m0 + wm * 32 + mt * 16 + grp + hf * 8;
            int s = m & 2047, bb = m >> 11;
            int t = dir ? (2047 - s) : s;
            float* o = g_xproj + (((long)dir * SQ + t) * NB + bb) * NG + n0
                     + wn * 32 + tg * 2;
#pragma unroll
            for (int nt = 0; nt < 4; nt++) {
                float2 v;
                v.x = acc[mt][nt][hf * 2 + 0] + bias[nt][0];
                v.y = acc[mt][nt][hf * 2 + 1] + bias[nt][1];
                *(float2*)(o + nt * 8) = v;
            }
        }
    }
}

// ---------------- K2a: cluster BiLSTM (R11 version — best measured) --------
__global__ void __launch_bounds__(256, 1) __cluster_dims__(16, 1, 1)
k_lstm_cl(const float* __restrict__ Whhf, const float* __restrict__ Whhb,
          const int* __restrict__ utter)
{
    unsigned c;
    asm("mov.u32 %0, %%cluster_ctarank;" : "=r"(c));
    const int grp = blockIdx.x >> 4;
    const int dir = grp >> 2;
    const int bp  = grp & 3;
    const int j0  = (int)c * 24;
    const float* Whh = dir ? Whhb : Whhf;
    const int tid = threadIdx.x;
    const int wid = tid >> 5, lane = tid & 31;
    const int g2   = wid >> 1;
    const int half = wid & 1;
    const int jw   = j0 + half * 12;

    __shared__ __align__(16) float h_s[2][2][HD];
    __shared__ float gate_s[4][24][2];
    __shared__ float segmax_s[2][33][24];
    __shared__ __align__(8) unsigned long long mbar[2];

    for (int i = tid; i < 2 * 2 * HD; i += 256) (&h_s[0][0][0])[i] = 0.f;
    for (int i = tid; i < 2 * 33 * 24; i += 256) (&segmax_s[0][0][0])[i] = 0.f;

    const unsigned mb0 = smem_u32(&mbar[0]);
    const unsigned mb1 = smem_u32(&mbar[1]);
    if (tid == 0) {
        asm volatile("mbarrier.init.shared.b64 [%0], %1;" :: "r"(mb0), "r"(1u) : "memory");
        asm volatile("mbarrier.init.shared.b64 [%0], %1;" :: "r"(mb1), "r"(1u) : "memory");
    }
    __syncthreads();
    if (tid == 0) {
        asm volatile("mbarrier.arrive.expect_tx.shared.b64 _, [%0], %1;" :: "r"(mb0), "r"(3072u) : "memory");
        asm volatile("mbarrier.arrive.expect_tx.shared.b64 _, [%0], %1;" :: "r"(mb1), "r"(3072u) : "memory");
    }

    unsigned long long wp[12][6];
#pragma unroll
    for (int i = 0; i < 12; i++) {
        const float* wr = Whh + (long)(g2 * HD + jw + i) * HD + lane * 2;
#pragma unroll
        for (int q = 0; q < 6; q++)
            wp[i][q] = *(const unsigned long long*)(wr + 64 * q);
    }

    const int jj_a = tid >> 1, b2_a = tid & 1;
    const int batch_a = bp * 2 + b2_a;
    float c_state = 0.f;

    __syncthreads();
    asm volatile("barrier.cluster.arrive.aligned;" ::: "memory");
    asm volatile("barrier.cluster.wait.aligned;" ::: "memory");

    for (int t = 0; t < SQ; t++) {
        float xp0 = 0.f, xp1 = 0.f, xp2 = 0.f, xp3 = 0.f;
        int useg = 0;
        if (tid < 48) {
            int pos = dir ? (SQ - 1 - t) : t;
            const float* xb = g_xproj +
                ((((long)dir * SQ + t) * NB + batch_a) * NG) + j0 + jj_a;
            xp0 = xb[0]; xp1 = xb[HD]; xp2 = xb[2 * HD]; xp3 = xb[3 * HD];
            int u = utter[batch_a * SQ + pos];
            useg = u > 0 ? u : 0;
        }

        if (t > 0) {
            unsigned mb = ((t - 1) & 1) ? mb1 : mb0;
            mbar_wait(mb, ((unsigned)(t - 1) >> 1) & 1u);
            if (tid == 0)
                asm volatile("mbarrier.arrive.expect_tx.shared.b64 _, [%0], %1;"
                             :: "r"(mb), "r"(3072u) : "memory");
        }

        const int br = (t + 1) & 1;
#pragma unroll
        for (int b2 = 0; b2 < 2; b2++) {
            unsigned long long p2[12];
#pragma unroll
            for (int i = 0; i < 12; i++) p2[i] = 0ull;
#pragma unroll
            for (int q = 0; q < 6; q++) {
                unsigned long long hq =
                    *(const unsigned long long*)&h_s[br][b2][lane * 2 + 64 * q];
#pragma unroll
                for (int i = 0; i < 12; i++)
                    p2[i] = fma2(wp[i][q], hq, p2[i]);
            }
#pragma unroll
            for (int i = 0; i < 12; i++) {
                float2 f = upk2(p2[i]);
                float v = f.x + f.y;
                v += __shfl_xor_sync(0xffffffffu, v, 16);
                v += __shfl_xor_sync(0xffffffffu, v, 8);
                v += __shfl_xor_sync(0xffffffffu, v, 4);
                v += __shfl_xor_sync(0xffffffffu, v, 2);
                v += __shfl_xor_sync(0xffffffffu, v, 1);
                if (lane == 0) gate_s[g2][half * 12 + i][b2] = v;
            }
        }
        __syncthreads();

        if (tid < 48) {
            float vi = gate_s[0][jj_a][b2_a] + xp0;
            float vf = gate_s[1][jj_a][b2_a] + xp1;
            float vg = gate_s[2][jj_a][b2_a] + xp2;
            float vo = gate_s[3][jj_a][b2_a] + xp3;
            float si = 1.f / (1.f + __expf(-vi));
            float sf = 1.f / (1.f + __expf(-vf));
            float so = 1.f / (1.f + __expf(-vo));
            float tg, tc;
            asm("tanh.approx.f32 %0, %1;" : "=f"(tg) : "f"(vg));
            c_state = sf * c_state + si * tg;
            asm("tanh.approx.f32 %0, %1;" : "=f"(tc) : "f"(c_state));
            float h = so * tc;

            unsigned val   = __float_as_uint(h);
            unsigned laddr = smem_u32(&h_s[t & 1][b2_a][j0 + jj_a]);
            unsigned lmbar = (t & 1) ? mb1 : mb0;
#pragma unroll
            for (int p = 0; p < 16; p++) {
                unsigned ra, rb;
                asm("mapa.shared::cluster.u32 %0, %1, %2;" : "=r"(ra) : "r"(laddr), "r"(p));
                asm("mapa.shared::cluster.u32 %0, %1, %2;" : "=r"(rb) : "r"(lmbar), "r"(p));
                asm volatile(
                    "st.async.shared::cluster.mbarrier::complete_tx::bytes.u32 [%0], %1, [%2];"
                    :: "r"(ra), "r"(val), "r"(rb) : "memory");
            }
            float* sm = &segmax_s[b2_a][useg][jj_a];
            *sm = fmaxf(*sm, h);
        }
    }

    mbar_wait(mb1, ((unsigned)(SQ - 1) >> 1) & 1u);

    if (tid < 48) {
        for (int u = 1; u <= NU; u++)
            g_mp[(batch_a * NU + (u - 1)) * HDIM + dir * HD + j0 + jj_a] =
                segmax_s[b2_a][u][jj_a];
    }
}

// ---------------- K2b: fallback BiLSTM (R8 version, L2 flag exchange) ------
__global__ void __launch_bounds__(256, 1) k_lstm(
    const float* __restrict__ Whhf, const float* __restrict__ Whhb,
    const int* __restrict__ utter)
{
    const int grp = blockIdx.x >> 4;
    const int c   = blockIdx.x & 15;
    const int dir = grp >> 2;
    const int bp  = grp & 3;
    const int j0  = c * 24;
    const float* Whh = dir ? Whhb : Whhf;
    const int tid = threadIdx.x;
    const int wid = tid >> 5, lane = tid & 31;
    const int g2   = wid >> 1;
    const int half = wid & 1;
    const int jw   = j0 + half * 12;

    __shared__ __align__(16) float h_s[2][HD];
    __shared__ float gate_s[4][24][2];
    __shared__ float segmax_s[2][33][24];

    for (int i = tid; i < 2 * HD; i += 256) (&h_s[0][0])[i] = 0.f;
    for (int i = tid; i < 2 * 33 * 24; i += 256) (&segmax_s[0][0][0])[i] = 0.f;

    unsigned long long wp[12][6];
#pragma unroll
    for (int i = 0; i < 12; i++) {
        const float* wr = Whh + (long)(g2 * HD + jw + i) * HD + lane * 2;
#pragma unroll
        for (int q = 0; q < 6; q++)
            wp[i][q] = *(const unsigned long long*)(wr + 64 * q);
    }

    const int jj_a = tid >> 1, b2_a = tid & 1;
    const int batch_a = bp * 2 + b2_a;
    float c_state = 0.f;
    unsigned* flags = g_flag + grp * 16 * 32;
    float* hbase = g_hbuf + grp * 2 * 2 * HD;

    __syncthreads();

    for (int t = 0; t < SQ; t++) {
        float xp0 = 0.f, xp1 = 0.f, xp2 = 0.f, xp3 = 0.f;
        int useg = 0;
        if (tid < 48) {
            int pos = dir ? (SQ - 1 - t) : t;
            const float* xb = g_xproj +
                ((((long)dir * SQ + t) * NB + batch_a) * NG) + j0 + jj_a;
            xp0 = xb[0]; xp1 = xb[HD]; xp2 = xb[2 * HD]; xp3 = xb[3 * HD];
            int u = utter[batch_a * SQ + pos];
            useg = u > 0 ? u : 0;
        }

#pragma unroll
        for (int b2 = 0; b2 < 2; b2++) {
            unsigned long long p2[12];
#pragma unroll
            for (int i = 0; i < 12; i++) p2[i] = 0ull;
#pragma unroll
            for (int q = 0; q < 6; q++) {
                unsigned long long hq =
                    *(const unsigned long long*)&h_s[b2][lane * 2 + 64 * q];
#pragma unroll
                for (int i = 0; i < 12; i++)
                    p2[i] = fma2(wp[i][q], hq, p2[i]);
            }
#pragma unroll
            for (int i = 0; i < 12; i++) {
                float2 f = upk2(p2[i]);
                float v = f.x + f.y;
                v += __shfl_xor_sync(0xffffffffu, v, 16);
                v += __shfl_xor_sync(0xffffffffu, v, 8);
                v += __shfl_xor_sync(0xffffffffu, v, 4);
                v += __shfl_xor_sync(0xffffffffu, v, 2);
                v += __shfl_xor_sync(0xffffffffu, v, 1);
                if (lane == 0) gate_s[g2][half * 12 + i][b2] = v;
            }
        }
        __syncthreads();

        if (tid < 48) {
            float vi = gate_s[0][jj_a][b2_a] + xp0;
            float vf = gate_s[1][jj_a][b2_a] + xp1;
            float vg = gate_s[2][jj_a][b2_a] + xp2;
            float vo = gate_s[3][jj_a][b2_a] + xp3;
            float si = 1.f / (1.f + __expf(-vi));
            float sf = 1.f / (1.f + __expf(-vf));
            float so = 1.f / (1.f + __expf(-vo));
            float tg, tc;
            asm("tanh.approx.f32 %0, %1;" : "=f"(tg) : "f"(vg));
            c_state = sf * c_state + si * tg;
            asm("tanh.approx.f32 %0, %1;" : "=f"(tc) : "f"(c_state));
            float h = so * tc;
            __stcg(hbase + (t & 1) * 2 * HD + b2_a * HD + j0 + jj_a, h);
            float* sm = &segmax_s[b2_a][useg][jj_a];
            *sm = fmaxf(*sm, h);
        }
        __syncthreads();

        if (tid == 0) {
            asm volatile("st.release.gpu.global.u32 [%0], %1;"
                         :: "l"(flags + c * 32), "r"((unsigned)(t + 1)) : "memory");
        }
        if (wid == 0) {
            unsigned tgt = (unsigned)(t + 1);
            const unsigned* fp = flags + lane * 32;
            bool ok;
            do {
                unsigned v = tgt;
                if (lane < 16)
                    asm volatile("ld.acquire.gpu.global.u32 %0, [%1];"
                                 : "=r"(v) : "l"(fp) : "memory");
                ok = __all_sync(0xffffffffu, v >= tgt);
            } while (!ok);
        }
        __syncthreads();

        if (tid < 192) {
            const float4* src = (const float4*)(hbase + (t & 1) * 2 * HD);
            ((float4*)(&h_s[0][0]))[tid] = __ldcg(src + tid);
        }
        __syncthreads();
    }

    if (tid < 48) {
        for (int u = 1; u <= NU; u++)
            g_mp[(batch_a * NU + (u - 1)) * HDIM + dir * HD + j0 + jj_a] =
                segmax_s[b2_a][u][jj_a];
    }
}

// ---------------- K3: topic softmax routing ---------------------------------
__global__ void __launch_bounds__(256) k_route(
    const float* __restrict__ tw, const float* __restrict__ tb,
    const float* __restrict__ table)
{
    const int b = blockIdx.x >> 5;
    const int u = blockIdx.x & 31;
    __shared__ float mp_s[768];
    __shared__ float lp_s[4][64];
    __shared__ float l_s[64], e_s[64];
    const int tid = threadIdx.x;
    const float* mpr = g_mp + (b * NU + u) * HDIM;
    for (int i = tid; i < 192; i += 256)
        ((float4*)mp_s)[i] = ((const float4*)mpr)[i];
    __syncthreads();
    {
        const int topic = tid & 63, slice = tid >> 6;
        float acc = 0.f;
        const float* wr = tw + topic * 768 + slice * 192;
        const float* ms = mp_s + slice * 192;
        for (int k = 0; k < 192; k += 4) {
            float4 wv = *(const float4*)(wr + k);
            acc = fmaf(wv.x, ms[k], acc);
            acc = fmaf(wv.y, ms[k + 1], acc);
            acc = fmaf(wv.z, ms[k + 2], acc);
            acc = fmaf(wv.w, ms[k + 3], acc);
        }
        lp_s[slice][topic] = acc;
    }
    __syncthreads();
    if (tid < 64)
        l_s[tid] = lp_s[0][tid] + lp_s[1][tid] + lp_s[2][tid] + lp_s[3][tid] + tb[tid];
    __syncthreads();
    if (tid < 64) {
        float mx = -1e30f;
        for (int i = 0; i < 64; i++) mx = fmaxf(mx, l_s[i]);
        e_s[tid] = expf(l_s[tid] - mx);
    }
    __syncthreads();
    float ssum = 0.f;
    for (int i = 0; i < 64; i++) ssum += e_s[i];
    float inv = 1.f / ssum;
    for (int h = tid; h < 768; h += 256) {
        float acc = 0.f;
        for (int tt = 0; tt < 64; tt++)
            acc = fmaf(e_s[tt], table[tt * 768 + h], acc);
        g_emb[(b * NU + u) * HDIM + h] = acc * inv;
    }
}

// ---------------- K4: scatter back to token positions -----------------------
__global__ void __launch_bounds__(256) k_scatter(
    const int* __restrict__ utter, float* __restrict__ out)
{
    int v = blockIdx.x * 256 + threadIdx.x;
    int m = v / 192;
    int h4 = v - m * 192;
    int u = __ldg(utter + m);
    float4 o = make_float4(0.f, 0.f, 0.f, 0.f);
    if (u != 0) {
        int idx = u > 0 ? u - 1 : -u - 1;
        if (idx > 31) idx = 31;
        int bb = m >> 11;
        float4 gv = *(const float4*)(g_emb + (bb * NU + idx) * HDIM + h4 * 4);
        float sc = u > 0 ? 1.f : 2.f;
        o.x = gv.x * sc; o.y = gv.y * sc; o.z = gv.z * sc; o.w = gv.w * sc;
    }
    ((float4*)out)[v] = o;
}

// ---------------- launch -----------------------------------------------------
extern "C" void kernel_launch(void* const* d_in, const int* in_sizes, int n_in,
                              void* d_out, int out_size)
{
    const float* X     = (const float*)d_in[0];
    const float* Wihf  = (const float*)d_in[1];
    const float* Whhf  = (const float*)d_in[2];
    const float* bihf  = (const float*)d_in[3];
    const float* bhhf  = (const float*)d_in[4];
    const float* Wihb  = (const float*)d_in[5];
    const float* Whhb  = (const float*)d_in[6];
    const float* bihb  = (const float*)d_in[7];
    const float* bhhb  = (const float*)d_in[8];
    const float* tw    = (const float*)d_in[9];
    const float* tb    = (const float*)d_in[10];
    const float* table = (const float*)d_in[11];
    const int*   utter = (const int*)d_in[12];

    // resolve device scratch addrs (host-side, capture-safe)
    static __nv_bfloat16 *xh_p = 0, *xl_p = 0, *wh_p = 0, *wl_p = 0;
    static int init_done = 0;
    if (!init_done) {
        cudaGetSymbolAddress((void**)&xh_p, g_xh);
        cudaGetSymbolAddress((void**)&xl_p, g_xl);
        cudaGetSymbolAddress((void**)&wh_p, g_wh);
        cudaGetSymbolAddress((void**)&wl_p, g_wl);
        init_done = 1;
    }

    // cluster probe (attr-free first; clusters independent so >=4 suffices)
    cudaFuncSetAttribute(k_lstm_cl,
                         cudaFuncAttributeNonPortableClusterSizeAllowed, 1);
    int ncl = 0;
    {
        cudaLaunchConfig_t cfg = {};
        cfg.gridDim  = dim3(128, 1, 1);
        cfg.blockDim = dim3(256, 1, 1);
        cfg.dynamicSmemBytes = 0;
        cfg.stream = 0;
        cfg.attrs = 0;
        cfg.numAttrs = 0;
        cudaError_t e1 = cudaOccupancyMaxActiveClusters(&ncl, k_lstm_cl, &cfg);
        if (e1 != cudaSuccess || ncl <= 0) {
            cudaGetLastError();
            cudaLaunchAttribute a[1];
            a[0].id = cudaLaunchAttributeClusterDimension;
            a[0].val.clusterDim.x = 16;
            a[0].val.clusterDim.y = 1;
            a[0].val.clusterDim.z = 1;
            cfg.attrs = a;
            cfg.numAttrs = 1;
            ncl = 0;
            cudaError_t e2 = cudaOccupancyMaxActiveClusters(&ncl, k_lstm_cl, &cfg);
            if (e2 != cudaSuccess) ncl = 0;
        }
        cudaGetLastError();
    }
    bool use_cl = (ncl >= 4);

    // launches: cvtX, cvtWf, cvtWb, gemm_mma(#4 for ncu), lstm, route, scatter
    k_cvt<<<49152, 256>>>(X, xh_p, xl_p, 16384 * 768);
    k_cvt<<<4608, 256>>>(Wihf, wh_p, wl_p, 1536 * 768);
    k_cvt<<<4608, 256>>>(Wihb, wh_p + 1536 * 768, wl_p + 1536 * 768, 1536 * 768);
    k_gemm_mma<<<dim3(12, 256, 2), 256>>>(
        xh_p, xl_p, wh_p, wl_p, bihf, bhhf, bihb, bhhb);
    if (use_cl) {
        k_lstm_cl<<<128, 256>>>(Whhf, Whhb, utter);
    } else {
        k_reset<<<16, 256>>>();
        k_lstm<<<128, 256>>>(Whhf, Whhb, utter);
    }
    k_route<<<256, 256>>>(tw, tb, table);
    k_scatter<<<12288, 256>>>(utter, (float*)d_out);
}